// round 13
// baseline (speedup 1.0000x reference)
#include <cuda_runtime.h>
#include <cuda_fp16.h>

#define D 64
#define ALPHA 0.2f
#define MAX_N 131072
#define MAX_E 2200000
#define SCAN_B 512

// Static scratch (BSS zero-init). Replay invariants: k_aggregate reads+zeros
// g_cnt; k_pre_hist zeroes g_total.
__device__ int     g_cnt[MAX_N];
__device__ int     g_rowptr[MAX_N];
__device__ int     g_total;
__device__ int     g_slot[MAX_E];     // per-edge within-row slot from hist
__device__ float4  g_rec[MAX_E];      // per-edge record: (w0, w1, col_bits, -)
__device__ float2  g_s1[MAX_N];       // per-node source-side scores (h0,h1)
__device__ float2  g_s2[MAX_N];       // per-node dest-side scores (h0,h1)

// Fused: blocks [0,nbE) do the edge histogram (slot assignment); blocks
// [nbE, nbE+nbW) do per-node score precompute (no x conversion anymore).
__global__ void k_pre_hist(const float* __restrict__ x,
                           const float* __restrict__ W,
                           const float* __restrict__ a,
                           const int* __restrict__ row,
                           int n, int E, int nbE) {
    int t = threadIdx.x;
    if ((int)blockIdx.x < nbE) {
        if (blockIdx.x == 0 && t == 0) g_total = 0;   // replay reset
        int i = blockIdx.x * blockDim.x + t;
        if (i < E) g_slot[i] = atomicAdd(&g_cnt[row[i]], 1);
        return;
    }
    __shared__ float v00[64], v01[64], v10[64], v11[64]; // W[h][j]*a[h][..j]
    if (t < 64) {
        float w0 = W[t], w1 = W[64 + t];
        v00[t] = w0 * a[t];
        v01[t] = w0 * a[64 + t];
        v10[t] = w1 * a[128 + t];
        v11[t] = w1 * a[192 + t];
    }
    __syncthreads();
    int b = blockIdx.x - nbE;
    int warp = (b * blockDim.x + t) >> 5;
    int lane = t & 31;
    if (warp >= n) return;
    float2 xv = reinterpret_cast<const float2*>(x)[warp * 32 + lane];
    int l2 = lane * 2;
    float s10 = xv.x * v00[l2] + xv.y * v00[l2 + 1];
    float s20 = xv.x * v01[l2] + xv.y * v01[l2 + 1];
    float s11 = xv.x * v10[l2] + xv.y * v10[l2 + 1];
    float s21 = xv.x * v11[l2] + xv.y * v11[l2 + 1];
    // 6-SHFL multi-value butterfly
    float u0 = (lane < 16 ? s10 : s20)
             + __shfl_xor_sync(0xffffffffu, (lane < 16 ? s20 : s10), 16);
    float u1 = (lane < 16 ? s11 : s21)
             + __shfl_xor_sync(0xffffffffu, (lane < 16 ? s21 : s11), 16);
    float v = ((lane & 8) ? u1 : u0)
            + __shfl_xor_sync(0xffffffffu, ((lane & 8) ? u0 : u1), 8);
    v += __shfl_xor_sync(0xffffffffu, v, 4);
    v += __shfl_xor_sync(0xffffffffu, v, 2);
    v += __shfl_xor_sync(0xffffffffu, v, 1);
    if (lane == 0)  g_s1[warp].x = v;
    if (lane == 8)  g_s1[warp].y = v;
    if (lane == 16) g_s2[warp].x = v;
    if (lane == 24) g_s2[warp].y = v;
}

// Single-pass scan: block-local exclusive scan of g_cnt; block claims its
// base with one atomicAdd. Row ranges are disjoint (sufficient); g_cnt kept
// as per-node degree for aggregate (which resets it).
__global__ void k_scan(int n) {
    __shared__ int sh[SCAN_B];
    __shared__ int base_sh;
    int t = threadIdx.x;
    int i = blockIdx.x * SCAN_B + t;
    int vv = (i < n) ? g_cnt[i] : 0;
    sh[t] = vv;
    __syncthreads();
    #pragma unroll
    for (int o = 1; o < SCAN_B; o <<= 1) {
        int tmp = (t >= o) ? sh[t - o] : 0;
        __syncthreads();
        sh[t] += tmp;
        __syncthreads();
    }
    if (t == SCAN_B - 1) base_sh = atomicAdd(&g_total, sh[t]);
    __syncthreads();
    if (i < n) g_rowptr[i] = base_sh + sh[t] - vv;
}

// Edge-parallel CSR fill (atomic-free): both head weights in fp32, packed
// with the column index into one 16-byte record (always 16B-aligned).
__global__ void k_scatter(const int* __restrict__ row,
                          const int* __restrict__ col, int E) {
    int i = blockIdx.x * blockDim.x + threadIdx.x;
    if (i >= E) return;
    int r = row[i], c = col[i];
    int pos = g_rowptr[r] + g_slot[i];
    float2 s1 = g_s1[r];
    float2 s2 = g_s2[c];
    float sc0 = s1.x + s2.x;
    float sc1 = s1.y + s2.y;
    float w0 = __expf(sc0 > 0.f ? sc0 : ALPHA * sc0);
    float w1 = __expf(sc1 > 0.f ? sc1 : ALPHA * sc1);
    g_rec[pos] = make_float4(w0, w1, __int_as_float(c), 0.f);
}

// One warp per node. fp32 everywhere: per edge = 1 LDG.128 record +
// 1 LDG.64 x-gather + 4 FFMA + 2 FADD (no converts). Independent
// iterations; unroll-4 keeps 4 gathers in flight. Resets g_cnt for replay.
__global__ void k_aggregate(const float* __restrict__ x,
                            float* __restrict__ out, int n) {
    int warp = (blockIdx.x * blockDim.x + threadIdx.x) >> 5;
    int lane = threadIdx.x & 31;
    if (warp >= n) return;
    int beg = g_rowptr[warp];
    int deg = g_cnt[warp];
    if (lane == 0) g_cnt[warp] = 0;
    const float2* __restrict__ x2 = reinterpret_cast<const float2*>(x);
    float a00 = 0.f, a01 = 0.f, a10 = 0.f, a11 = 0.f;
    float rs0 = 0.f, rs1 = 0.f;
    #pragma unroll 4
    for (int j = 0; j < deg; j++) {
        float4 r = g_rec[beg + j];
        int c = __float_as_int(r.z);
        float2 xv = x2[c * 32 + lane];
        a00 += r.x * xv.x; a01 += r.x * xv.y;
        a10 += r.y * xv.x; a11 += r.y * xv.y;
        rs0 += r.x; rs1 += r.y;
    }
    float i0 = 0.5f / rs0, i1 = 0.5f / rs1;
    float2 o;
    o.x = a00 * i0 + a10 * i1;
    o.y = a01 * i0 + a11 * i1;
    reinterpret_cast<float2*>(out)[warp * 32 + lane] = o;
}

extern "C" void kernel_launch(void* const* d_in, const int* in_sizes, int n_in,
                              void* d_out, int out_size) {
    const float* x  = (const float*)d_in[0];
    const int*   ei = (const int*)d_in[1];
    const float* W  = (const float*)d_in[2];
    const float* a  = (const float*)d_in[3];
    float* out = (float*)d_out;

    int n = in_sizes[0] / D;
    int E = in_sizes[1] / 2;
    const int* row = ei;
    const int* col = ei + E;

    const int T = 256;
    int nbE = (E + T - 1) / T;
    int nbW = (n * 32 + T - 1) / T;          // one warp per node
    int nbS = (n + SCAN_B - 1) / SCAN_B;

    k_pre_hist<<<nbE + nbW, T>>>(x, W, a, row, n, E, nbE);
    k_scan<<<nbS, SCAN_B>>>(n);
    k_scatter<<<nbE, T>>>(row, col, E);
    k_aggregate<<<nbW, T>>>(x, out, n);
}

// round 14
// speedup vs baseline: 1.2503x; 1.2503x over previous
#include <cuda_runtime.h>
#include <cuda_fp16.h>

#define D 64
#define ALPHA 0.2f
#define MAX_N 131072
#define MAX_E 2200000
#define SCAN_B 512

// Static scratch (BSS zero-init). Replay invariants: k_aggregate reads+zeros
// g_cnt; k_pre_hist zeroes g_total.
__device__ int     g_cnt[MAX_N];
__device__ int     g_rowptr[MAX_N];
__device__ int     g_total;
__device__ int     g_slot[MAX_E];     // per-edge within-row slot from hist
__device__ __align__(16) unsigned long long g_rec[MAX_E]; // (col<<32)|half2(w0,w1)
__device__ float2  g_s1[MAX_N];       // per-node source-side scores (h0,h1)
__device__ float2  g_s2[MAX_N];       // per-node dest-side scores (h0,h1)
__device__ __half2 g_xh[MAX_N * 32];  // fp16 copy of x, 2 feats per lane

// Fused: blocks [0,nbE) do the edge histogram; blocks [nbE,...) do per-node
// scores, FOUR nodes per warp so each thread has 4 independent DRAM loads in
// flight (the x read is a latency-limited cold stream at MLP=1 otherwise).
__global__ void k_pre_hist(const float* __restrict__ x,
                           const float* __restrict__ W,
                           const float* __restrict__ a,
                           const int* __restrict__ row,
                           int n, int E, int nbE) {
    int t = threadIdx.x;
    if ((int)blockIdx.x < nbE) {
        if (blockIdx.x == 0 && t == 0) g_total = 0;   // replay reset
        int i = blockIdx.x * blockDim.x + t;
        if (i < E) g_slot[i] = atomicAdd(&g_cnt[row[i]], 1);
        return;
    }
    __shared__ float v00[64], v01[64], v10[64], v11[64]; // W[h][j]*a[h][..j]
    if (t < 64) {
        float w0 = W[t], w1 = W[64 + t];
        v00[t] = w0 * a[t];
        v01[t] = w0 * a[64 + t];
        v10[t] = w1 * a[128 + t];
        v11[t] = w1 * a[192 + t];
    }
    __syncthreads();
    int b = blockIdx.x - nbE;
    int warp = (b * blockDim.x + t) >> 5;   // warp handles nodes 4w..4w+3
    int lane = t & 31;
    int base = warp * 4;
    if (base >= n) return;
    const float2* __restrict__ x2 = reinterpret_cast<const float2*>(x);
    float2 xv[4];
    int nk = min(4, n - base);
    #pragma unroll
    for (int k = 0; k < 4; k++)
        if (k < nk) xv[k] = x2[(base + k) * 32 + lane];   // 4 indep loads
    int l2 = lane * 2;
    float c00a = v00[l2], c00b = v00[l2 + 1];
    float c01a = v01[l2], c01b = v01[l2 + 1];
    float c10a = v10[l2], c10b = v10[l2 + 1];
    float c11a = v11[l2], c11b = v11[l2 + 1];
    #pragma unroll
    for (int k = 0; k < 4; k++) {
        if (k >= nk) break;
        g_xh[(base + k) * 32 + lane] = __floats2half2_rn(xv[k].x, xv[k].y);
        float s10 = xv[k].x * c00a + xv[k].y * c00b;
        float s20 = xv[k].x * c01a + xv[k].y * c01b;
        float s11 = xv[k].x * c10a + xv[k].y * c10b;
        float s21 = xv[k].x * c11a + xv[k].y * c11b;
        // 6-SHFL multi-value butterfly
        float u0 = (lane < 16 ? s10 : s20)
                 + __shfl_xor_sync(0xffffffffu, (lane < 16 ? s20 : s10), 16);
        float u1 = (lane < 16 ? s11 : s21)
                 + __shfl_xor_sync(0xffffffffu, (lane < 16 ? s21 : s11), 16);
        float v = ((lane & 8) ? u1 : u0)
                + __shfl_xor_sync(0xffffffffu, ((lane & 8) ? u0 : u1), 8);
        v += __shfl_xor_sync(0xffffffffu, v, 4);
        v += __shfl_xor_sync(0xffffffffu, v, 2);
        v += __shfl_xor_sync(0xffffffffu, v, 1);
        if (lane == 0)  g_s1[base + k].x = v;
        if (lane == 8)  g_s1[base + k].y = v;
        if (lane == 16) g_s2[base + k].x = v;
        if (lane == 24) g_s2[base + k].y = v;
    }
}

// Single-pass scan: block-local exclusive scan of g_cnt; block claims its
// base with one atomicAdd. Row ranges are disjoint (sufficient); g_cnt kept
// as per-node degree for aggregate (which resets it).
__global__ void k_scan(int n) {
    __shared__ int sh[SCAN_B];
    __shared__ int base_sh;
    int t = threadIdx.x;
    int i = blockIdx.x * SCAN_B + t;
    int vv = (i < n) ? g_cnt[i] : 0;
    sh[t] = vv;
    __syncthreads();
    #pragma unroll
    for (int o = 1; o < SCAN_B; o <<= 1) {
        int tmp = (t >= o) ? sh[t - o] : 0;
        __syncthreads();
        sh[t] += tmp;
        __syncthreads();
    }
    if (t == SCAN_B - 1) base_sh = atomicAdd(&g_total, sh[t]);
    __syncthreads();
    if (i < n) g_rowptr[i] = base_sh + sh[t] - vv;
}

// Edge-parallel CSR fill (atomic-free): both head weights in fp16, packed
// with the column index into one 8-byte record.
__global__ void k_scatter(const int* __restrict__ row,
                          const int* __restrict__ col, int E) {
    int i = blockIdx.x * blockDim.x + threadIdx.x;
    if (i >= E) return;
    int r = row[i], c = col[i];
    int pos = g_rowptr[r] + g_slot[i];
    float2 s1 = g_s1[r];
    float2 s2 = g_s2[c];
    float sc0 = s1.x + s2.x;
    float sc1 = s1.y + s2.y;
    float w0 = __expf(sc0 > 0.f ? sc0 : ALPHA * sc0);
    float w1 = __expf(sc1 > 0.f ? sc1 : ALPHA * sc1);
    __half2 wh = __floats2half2_rn(w0, w1);
    unsigned wbits = *reinterpret_cast<unsigned*>(&wh);
    g_rec[pos] = ((unsigned long long)(unsigned)c << 32) | wbits;
}

__device__ __forceinline__ void agg_one(unsigned long long r, int lane,
                                        float& a00, float& a01, float& a10,
                                        float& a11, float& rs0, float& rs1) {
    unsigned lo = (unsigned)r;
    int c = (int)(r >> 32);
    float2 w = __half22float2(*reinterpret_cast<__half2*>(&lo));
    float2 xf = __half22float2(g_xh[c * 32 + lane]);
    a00 += w.x * xf.x; a01 += w.x * xf.y;
    a10 += w.y * xf.x; a11 += w.y * xf.y;
    rs0 += w.x; rs1 += w.y;
}

// One warp per node. Manual 4-edge main iteration: two LDG.128 record loads
// plus four independent x gathers in flight (explicit structure; do NOT rely
// on compiler unrolling — that was the R13 failure). deg from g_cnt, which
// is reset here for the next graph replay.
__global__ void k_aggregate(float* __restrict__ out, int n) {
    int warp = (blockIdx.x * blockDim.x + threadIdx.x) >> 5;
    int lane = threadIdx.x & 31;
    if (warp >= n) return;
    int beg = g_rowptr[warp];
    int deg = g_cnt[warp];
    if (lane == 0) g_cnt[warp] = 0;
    int end = beg + deg;
    float a00 = 0.f, a01 = 0.f, a10 = 0.f, a11 = 0.f;
    float rs0 = 0.f, rs1 = 0.f;

    int e = beg;
    if (e < end && (e & 1)) {              // align to 16B
        agg_one(g_rec[e], lane, a00, a01, a10, a11, rs0, rs1);
        e++;
    }
    for (; e + 3 < end; e += 4) {          // 4-wide: 2 LDG.128 + 4 gathers
        uint4 qa = *reinterpret_cast<const uint4*>(&g_rec[e]);
        uint4 qb = *reinterpret_cast<const uint4*>(&g_rec[e + 2]);
        int c0 = (int)qa.y, c1 = (int)qa.w;
        int c2 = (int)qb.y, c3 = (int)qb.w;
        float2 x0 = __half22float2(g_xh[c0 * 32 + lane]);
        float2 x1 = __half22float2(g_xh[c1 * 32 + lane]);
        float2 x2 = __half22float2(g_xh[c2 * 32 + lane]);
        float2 x3 = __half22float2(g_xh[c3 * 32 + lane]);
        float2 w0 = __half22float2(*reinterpret_cast<__half2*>(&qa.x));
        float2 w1 = __half22float2(*reinterpret_cast<__half2*>(&qa.z));
        float2 w2 = __half22float2(*reinterpret_cast<__half2*>(&qb.x));
        float2 w3 = __half22float2(*reinterpret_cast<__half2*>(&qb.z));
        a00 += w0.x * x0.x; a01 += w0.x * x0.y;
        a10 += w0.y * x0.x; a11 += w0.y * x0.y;
        rs0 += w0.x; rs1 += w0.y;
        a00 += w1.x * x1.x; a01 += w1.x * x1.y;
        a10 += w1.y * x1.x; a11 += w1.y * x1.y;
        rs0 += w1.x; rs1 += w1.y;
        a00 += w2.x * x2.x; a01 += w2.x * x2.y;
        a10 += w2.y * x2.x; a11 += w2.y * x2.y;
        rs0 += w2.x; rs1 += w2.y;
        a00 += w3.x * x3.x; a01 += w3.x * x3.y;
        a10 += w3.y * x3.x; a11 += w3.y * x3.y;
        rs0 += w3.x; rs1 += w3.y;
    }
    for (; e + 1 < end; e += 2) {          // pair
        uint4 q = *reinterpret_cast<const uint4*>(&g_rec[e]);
        int c0 = (int)q.y, c1 = (int)q.w;
        float2 w0 = __half22float2(*reinterpret_cast<__half2*>(&q.x));
        float2 w1 = __half22float2(*reinterpret_cast<__half2*>(&q.z));
        float2 x0 = __half22float2(g_xh[c0 * 32 + lane]);
        float2 x1 = __half22float2(g_xh[c1 * 32 + lane]);
        a00 += w0.x * x0.x; a01 += w0.x * x0.y;
        a10 += w0.y * x0.x; a11 += w0.y * x0.y;
        rs0 += w0.x; rs1 += w0.y;
        a00 += w1.x * x1.x; a01 += w1.x * x1.y;
        a10 += w1.y * x1.x; a11 += w1.y * x1.y;
        rs0 += w1.x; rs1 += w1.y;
    }
    if (e < end)                            // tail
        agg_one(g_rec[e], lane, a00, a01, a10, a11, rs0, rs1);

    float i0 = 0.5f / rs0, i1 = 0.5f / rs1;
    float2 o;
    o.x = a00 * i0 + a10 * i1;
    o.y = a01 * i0 + a11 * i1;
    reinterpret_cast<float2*>(out)[warp * 32 + lane] = o;
}

extern "C" void kernel_launch(void* const* d_in, const int* in_sizes, int n_in,
                              void* d_out, int out_size) {
    const float* x  = (const float*)d_in[0];
    const int*   ei = (const int*)d_in[1];
    const float* W  = (const float*)d_in[2];
    const float* a  = (const float*)d_in[3];
    float* out = (float*)d_out;

    int n = in_sizes[0] / D;
    int E = in_sizes[1] / 2;
    const int* row = ei;
    const int* col = ei + E;

    const int T = 256;
    int nbE = (E + T - 1) / T;
    int nodes4 = (n + 3) / 4;                    // 4 nodes per warp in pre
    int nbP = (nodes4 * 32 + T - 1) / T;
    int nbW = (n * 32 + T - 1) / T;              // one warp per node
    int nbS = (n + SCAN_B - 1) / SCAN_B;

    k_pre_hist<<<nbE + nbP, T>>>(x, W, a, row, n, E, nbE);
    k_scan<<<nbS, SCAN_B>>>(n);
    k_scatter<<<nbE, T>>>(row, col, E);
    k_aggregate<<<nbW, T>>>(out, n);
}

// round 15
// speedup vs baseline: 2.4377x; 1.9496x over previous
#include <cuda_runtime.h>
#include <cuda_fp16.h>

#define D 64
#define ALPHA 0.2f
#define MAX_N 131072
#define MAX_E 2200000
#define SCAN_B 512

// Static scratch (BSS zero-init). Replay invariants: k_aggregate reads+zeros
// g_cnt; k_pre_hist zeroes g_total.
__device__ int     g_cnt[MAX_N];
__device__ int     g_rowptr[MAX_N];
__device__ int     g_total;
__device__ int     g_slot[MAX_E];     // per-edge within-row slot from hist
__device__ __align__(16) unsigned long long g_rec[MAX_E]; // (col<<32)|half2(w0,w1)
__device__ float2  g_s1[MAX_N];       // per-node source-side scores (h0,h1)
__device__ float2  g_s2[MAX_N];       // per-node dest-side scores (h0,h1)
__device__ __half2 g_xh[MAX_N * 32];  // fp16 copy of x, 2 feats per lane

// Fused: blocks [0,nbE) do the edge histogram; blocks [nbE,...) do per-node
// scores, FOUR nodes per warp so each thread has 4 independent DRAM loads in
// flight (validated in R14: non-aggregate time dropped ~20us).
__global__ void k_pre_hist(const float* __restrict__ x,
                           const float* __restrict__ W,
                           const float* __restrict__ a,
                           const int* __restrict__ row,
                           int n, int E, int nbE) {
    int t = threadIdx.x;
    if ((int)blockIdx.x < nbE) {
        if (blockIdx.x == 0 && t == 0) g_total = 0;   // replay reset
        int i = blockIdx.x * blockDim.x + t;
        if (i < E) g_slot[i] = atomicAdd(&g_cnt[row[i]], 1);
        return;
    }
    __shared__ float v00[64], v01[64], v10[64], v11[64]; // W[h][j]*a[h][..j]
    if (t < 64) {
        float w0 = W[t], w1 = W[64 + t];
        v00[t] = w0 * a[t];
        v01[t] = w0 * a[64 + t];
        v10[t] = w1 * a[128 + t];
        v11[t] = w1 * a[192 + t];
    }
    __syncthreads();
    int b = blockIdx.x - nbE;
    int warp = (b * blockDim.x + t) >> 5;   // warp handles nodes 4w..4w+3
    int lane = t & 31;
    int base = warp * 4;
    if (base >= n) return;
    const float2* __restrict__ x2 = reinterpret_cast<const float2*>(x);
    float2 xv[4];
    int nk = min(4, n - base);
    #pragma unroll
    for (int k = 0; k < 4; k++)
        if (k < nk) xv[k] = x2[(base + k) * 32 + lane];   // 4 indep loads
    int l2 = lane * 2;
    float c00a = v00[l2], c00b = v00[l2 + 1];
    float c01a = v01[l2], c01b = v01[l2 + 1];
    float c10a = v10[l2], c10b = v10[l2 + 1];
    float c11a = v11[l2], c11b = v11[l2 + 1];
    #pragma unroll
    for (int k = 0; k < 4; k++) {
        if (k >= nk) break;
        g_xh[(base + k) * 32 + lane] = __floats2half2_rn(xv[k].x, xv[k].y);
        float s10 = xv[k].x * c00a + xv[k].y * c00b;
        float s20 = xv[k].x * c01a + xv[k].y * c01b;
        float s11 = xv[k].x * c10a + xv[k].y * c10b;
        float s21 = xv[k].x * c11a + xv[k].y * c11b;
        // 6-SHFL multi-value butterfly
        float u0 = (lane < 16 ? s10 : s20)
                 + __shfl_xor_sync(0xffffffffu, (lane < 16 ? s20 : s10), 16);
        float u1 = (lane < 16 ? s11 : s21)
                 + __shfl_xor_sync(0xffffffffu, (lane < 16 ? s21 : s11), 16);
        float v = ((lane & 8) ? u1 : u0)
                + __shfl_xor_sync(0xffffffffu, ((lane & 8) ? u0 : u1), 8);
        v += __shfl_xor_sync(0xffffffffu, v, 4);
        v += __shfl_xor_sync(0xffffffffu, v, 2);
        v += __shfl_xor_sync(0xffffffffu, v, 1);
        if (lane == 0)  g_s1[base + k].x = v;
        if (lane == 8)  g_s1[base + k].y = v;
        if (lane == 16) g_s2[base + k].x = v;
        if (lane == 24) g_s2[base + k].y = v;
    }
}

// Single-pass scan: block-local exclusive scan of g_cnt; block claims its
// base with one atomicAdd. Row ranges are disjoint (sufficient); g_cnt kept
// as per-node degree for aggregate (which resets it).
__global__ void k_scan(int n) {
    __shared__ int sh[SCAN_B];
    __shared__ int base_sh;
    int t = threadIdx.x;
    int i = blockIdx.x * SCAN_B + t;
    int vv = (i < n) ? g_cnt[i] : 0;
    sh[t] = vv;
    __syncthreads();
    #pragma unroll
    for (int o = 1; o < SCAN_B; o <<= 1) {
        int tmp = (t >= o) ? sh[t - o] : 0;
        __syncthreads();
        sh[t] += tmp;
        __syncthreads();
    }
    if (t == SCAN_B - 1) base_sh = atomicAdd(&g_total, sh[t]);
    __syncthreads();
    if (i < n) g_rowptr[i] = base_sh + sh[t] - vv;
}

// Edge-parallel CSR fill (atomic-free): both head weights in fp16, packed
// with the column index into one 8-byte record.
__global__ void k_scatter(const int* __restrict__ row,
                          const int* __restrict__ col, int E) {
    int i = blockIdx.x * blockDim.x + threadIdx.x;
    if (i >= E) return;
    int r = row[i], c = col[i];
    int pos = g_rowptr[r] + g_slot[i];
    float2 s1 = g_s1[r];
    float2 s2 = g_s2[c];
    float sc0 = s1.x + s2.x;
    float sc1 = s1.y + s2.y;
    float w0 = __expf(sc0 > 0.f ? sc0 : ALPHA * sc0);
    float w1 = __expf(sc1 > 0.f ? sc1 : ALPHA * sc1);
    __half2 wh = __floats2half2_rn(w0, w1);
    unsigned wbits = *reinterpret_cast<unsigned*>(&wh);
    g_rec[pos] = ((unsigned long long)(unsigned)c << 32) | wbits;
}

// One warp per node — BYTE-IDENTICAL to the R12 aggregate (50.8us measured,
// issue-bound at 60%): head-align + pair loop + tail. Do not restructure;
// R11/R13/R14 all regressed when this loop was altered.
__global__ void k_aggregate(float* __restrict__ out, int n) {
    int warp = (blockIdx.x * blockDim.x + threadIdx.x) >> 5;
    int lane = threadIdx.x & 31;
    if (warp >= n) return;
    int beg = g_rowptr[warp];
    int deg = g_cnt[warp];
    if (lane == 0) g_cnt[warp] = 0;
    int end = beg + deg;
    float a00 = 0.f, a01 = 0.f, a10 = 0.f, a11 = 0.f;
    float rs0 = 0.f, rs1 = 0.f;

    int e = beg;
    if (e < end && (e & 1)) {          // head: align to even index
        unsigned long long r = g_rec[e];
        unsigned lo = (unsigned)r;
        int c = (int)(r >> 32);
        float2 w = __half22float2(*reinterpret_cast<__half2*>(&lo));
        float2 xf = __half22float2(g_xh[c * 32 + lane]);
        a00 += w.x * xf.x; a01 += w.x * xf.y;
        a10 += w.y * xf.x; a11 += w.y * xf.y;
        rs0 += w.x; rs1 += w.y;
        e++;
    }
    for (; e + 1 < end; e += 2) {      // aligned pair
        uint4 q = *reinterpret_cast<const uint4*>(&g_rec[e]);
        int c0 = (int)q.y, c1 = (int)q.w;
        float2 w0 = __half22float2(*reinterpret_cast<__half2*>(&q.x));
        float2 w1 = __half22float2(*reinterpret_cast<__half2*>(&q.z));
        float2 x0 = __half22float2(g_xh[c0 * 32 + lane]);
        float2 x1 = __half22float2(g_xh[c1 * 32 + lane]);
        a00 += w0.x * x0.x; a01 += w0.x * x0.y;
        a10 += w0.y * x0.x; a11 += w0.y * x0.y;
        rs0 += w0.x; rs1 += w0.y;
        a00 += w1.x * x1.x; a01 += w1.x * x1.y;
        a10 += w1.y * x1.x; a11 += w1.y * x1.y;
        rs0 += w1.x; rs1 += w1.y;
    }
    if (e < end) {                     // tail
        unsigned long long r = g_rec[e];
        unsigned lo = (unsigned)r;
        int c = (int)(r >> 32);
        float2 w = __half22float2(*reinterpret_cast<__half2*>(&lo));
        float2 xf = __half22float2(g_xh[c * 32 + lane]);
        a00 += w.x * xf.x; a01 += w.x * xf.y;
        a10 += w.y * xf.x; a11 += w.y * xf.y;
        rs0 += w.x; rs1 += w.y;
    }

    float i0 = 0.5f / rs0, i1 = 0.5f / rs1;
    float2 o;
    o.x = a00 * i0 + a10 * i1;
    o.y = a01 * i0 + a11 * i1;
    reinterpret_cast<float2*>(out)[warp * 32 + lane] = o;
}

extern "C" void kernel_launch(void* const* d_in, const int* in_sizes, int n_in,
                              void* d_out, int out_size) {
    const float* x  = (const float*)d_in[0];
    const int*   ei = (const int*)d_in[1];
    const float* W  = (const float*)d_in[2];
    const float* a  = (const float*)d_in[3];
    float* out = (float*)d_out;

    int n = in_sizes[0] / D;
    int E = in_sizes[1] / 2;
    const int* row = ei;
    const int* col = ei + E;

    const int T = 256;
    int nbE = (E + T - 1) / T;
    int nodes4 = (n + 3) / 4;                    // 4 nodes per warp in pre
    int nbP = (nodes4 * 32 + T - 1) / T;
    int nbW = (n * 32 + T - 1) / T;              // one warp per node
    int nbS = (n + SCAN_B - 1) / SCAN_B;

    k_pre_hist<<<nbE + nbP, T>>>(x, W, a, row, n, E, nbE);
    k_scan<<<nbS, SCAN_B>>>(n);
    k_scatter<<<nbE, T>>>(row, col, E);
    k_aggregate<<<nbW, T>>>(out, n);
}